// round 15
// baseline (speedup 1.0000x reference)
#include <cuda_runtime.h>
#include <cuda_fp16.h>
#include <cuda_bf16.h>
#include <cstdint>
#include <math.h>

// Problem sizes (fixed)
#define BATCH 4
#define TSEQ 2048
#define BT (BATCH*TSEQ)       // 8192
#define DMODEL 1024
#define NHEADS 16
#define DHEAD 64
#define DFF 4096
#define BOT 256
#define ABH 32
#define EPS 1e-6f

// -------- static scratch (allocation-free contract) --------
__device__ __align__(256) __half g_xn1h[BT*DMODEL];
__device__ __align__(256) __half g_qh[BT*DMODEL];
__device__ __align__(256) __half g_kh[BT*DMODEL];
__device__ __align__(256) __half g_vh[BT*DMODEL];
__device__ __align__(256) __half g_atth[BT*DMODEL];
__device__ float g_x1[BT*DMODEL];
__device__ __align__(256) __half g_n2h[BT*DMODEL];
__device__ __align__(256) __half g_hidh[BT*DFF];
__device__ __align__(256) __half g_ffnh[BT*DMODEL];
__device__ __align__(256) __half g_phh[BT*BOT];
__device__ float g_gpart[8*BATCH*DMODEL];
__device__ float g_ab[2*BATCH];
// single fp16 weight arena (converted per call)
#define HW_TOTAL_ELEMS 13107200
__device__ __align__(256) __half g_hWall[HW_TOTAL_ELEMS];

// ---------------- helpers ----------------
__device__ __forceinline__ uint32_t smem_u32(const void* p) {
    uint32_t a;
    asm("{ .reg .u64 t; cvta.to.shared.u64 t, %1; cvt.u32.u64 %0, t; }" : "=r"(a) : "l"(p));
    return a;
}
__device__ __forceinline__ void cp16(uint32_t daddr, const void* gptr) {
    asm volatile("cp.async.cg.shared.global [%0], [%1], 16;" :: "r"(daddr), "l"(gptr) : "memory");
}
#define CP_COMMIT() asm volatile("cp.async.commit_group;" ::: "memory")
#define CP_WAIT0()  asm volatile("cp.async.wait_group 0;" ::: "memory")

__device__ __forceinline__ void mma_f16(float& c0, float& c1, float& c2, float& c3,
                                        uint32_t a0, uint32_t a1, uint32_t a2, uint32_t a3,
                                        uint32_t b0, uint32_t b1) {
    asm volatile(
        "mma.sync.aligned.m16n8k16.row.col.f32.f16.f16.f32 "
        "{%0,%1,%2,%3}, {%4,%5,%6,%7}, {%8,%9}, {%0,%1,%2,%3};"
        : "+f"(c0), "+f"(c1), "+f"(c2), "+f"(c3)
        : "r"(a0), "r"(a1), "r"(a2), "r"(a3), "r"(b0), "r"(b1));
}
__device__ __forceinline__ void ldsm4(uint32_t& r0, uint32_t& r1, uint32_t& r2, uint32_t& r3,
                                      uint32_t a) {
    asm volatile("ldmatrix.sync.aligned.m8n8.x4.shared.b16 {%0,%1,%2,%3}, [%4];"
                 : "=r"(r0), "=r"(r1), "=r"(r2), "=r"(r3) : "r"(a));
}
__device__ __forceinline__ void ldsm4t(uint32_t& r0, uint32_t& r1, uint32_t& r2, uint32_t& r3,
                                       uint32_t a) {
    asm volatile("ldmatrix.sync.aligned.m8n8.x4.trans.shared.b16 {%0,%1,%2,%3}, [%4];"
                 : "=r"(r0), "=r"(r1), "=r"(r2), "=r"(r3) : "r"(a));
}
__device__ __forceinline__ uint32_t packh2(float a, float b) {
    __half2 h = __floats2half2_rn(a, b);
    return *reinterpret_cast<uint32_t*>(&h);
}

// ---------------- fused fp32 -> fp16 converter for all weights ----------------
struct SrcPtrs { const float4* p[8]; };

__global__ void __launch_bounds__(256) f2h_all_kernel(SrcPtrs sp, uint2* __restrict__ dst) {
    const int t = blockIdx.x * 256 + threadIdx.x;
#pragma unroll
    for (int j = 0; j < 4; j++) {
        int idx = t + j * 819200;
        int seg, base;
        if (idx < 1048576)      { seg = idx >> 18;                    base = seg << 18; }
        else if (idx < 3145728) { seg = 4 + ((idx - 1048576) >> 20);  base = 1048576 + ((seg - 4) << 20); }
        else                    { seg = 6 + ((idx - 3145728) >> 16);  base = 3145728 + ((seg - 6) << 16); }
        float4 v = sp.p[seg][idx - base];
        __half2 lo = __floats2half2_rn(v.x, v.y);
        __half2 hi = __floats2half2_rn(v.z, v.w);
        dst[idx] = make_uint2(*(uint32_t*)&lo, *(uint32_t*)&hi);
    }
}

// ============ fp16 mma.sync GEMM: C = A[M,K] @ B[N,K]^T (+epilogue) ============
// CTA 128x128, BK=64, 2-stage double buffer, 2 CTAs/SM, 1 sync per chunk.
#define SMSH 72
#define HMAT_BYTES (128 * SMSH * 2)
#define HSTAGE_BYTES (2 * HMAT_BYTES)
#define GEMMH_SMEM (2 * HSTAGE_BYTES)

template<int EPI, bool RESID, bool OUTH>
__device__ __forceinline__ void gemmh_body(const __half* __restrict__ A,
                                           const __half* __restrict__ B,
                                           const float* __restrict__ R,
                                           void* __restrict__ Cv,
                                           int N, int K, int bm, int bn,
                                           const __half* __restrict__ R2h = nullptr,
                                           const float* __restrict__ AB = nullptr) {
    extern __shared__ __half hsmem[];
    const uint32_t sbase = smem_u32(hsmem);

    const int tid = threadIdx.x;
    const int warp = tid >> 5;
    const int lane = tid & 31;
    const int g = lane >> 2;
    const int tg = lane & 3;
    const int sub = lane >> 3;
    const int rin = lane & 7;
    const int wm = (warp & 1) * 64;
    const int wn = (warp >> 1) * 32;

    const int NC = K >> 6;

    auto issue = [&](int kc) {
        const uint32_t ab = sbase + (kc & 1) * HSTAGE_BYTES;
        const uint32_t bb = ab + HMAT_BYTES;
        const int k0 = kc << 6;
#pragma unroll
        for (int i = 0; i < 4; i++) {
            int e = tid + i * 256;
            int r = e >> 3, q8 = e & 7;
            uint32_t soff = (uint32_t)(r * SMSH + q8 * 8) * 2;
            cp16(ab + soff, &A[(size_t)(bm + r) * K + k0 + q8 * 8]);
            cp16(bb + soff, &B[(size_t)(bn + r) * K + k0 + q8 * 8]);
        }
    };

    float acc[4][4][4];
#pragma unroll
    for (int i = 0; i < 4; i++)
#pragma unroll
        for (int j = 0; j < 4; j++)
#pragma unroll
            for (int l = 0; l < 4; l++) acc[i][j][l] = 0.f;

    issue(0); CP_COMMIT();

    for (int kc = 0; kc < NC; kc++) {
        CP_WAIT0();
        __syncthreads();
        if (kc + 1 < NC) {
            issue(kc + 1);
            CP_COMMIT();
        }

        const uint32_t sA = sbase + (kc & 1) * HSTAGE_BYTES;
        const uint32_t sB = sA + HMAT_BYTES;

#pragma unroll
        for (int ks = 0; ks < 4; ks++) {
            uint32_t af[4][4], bf[4][2];
#pragma unroll
            for (int mt = 0; mt < 4; mt++) {
                int row = wm + mt * 16 + rin + (sub & 1) * 8;
                int col = ks * 16 + (sub >> 1) * 8;
                ldsm4(af[mt][0], af[mt][1], af[mt][2], af[mt][3],
                      sA + (uint32_t)(row * SMSH + col) * 2);
            }
#pragma unroll
            for (int p = 0; p < 2; p++) {
                int nrow = wn + (2 * p + (sub >> 1)) * 8 + rin;
                int ncol = ks * 16 + (sub & 1) * 8;
                ldsm4(bf[2 * p][0], bf[2 * p][1], bf[2 * p + 1][0], bf[2 * p + 1][1],
                      sB + (uint32_t)(nrow * SMSH + ncol) * 2);
            }
#pragma unroll
            for (int mt = 0; mt < 4; mt++)
#pragma unroll
                for (int nt = 0; nt < 4; nt++)
                    mma_f16(acc[mt][nt][0], acc[mt][nt][1], acc[mt][nt][2], acc[mt][nt][3],
                            af[mt][0], af[mt][1], af[mt][2], af[mt][3],
                            bf[nt][0], bf[nt][1]);
        }
    }

#pragma unroll
    for (int mt = 0; mt < 4; mt++) {
#pragma unroll
        for (int nt = 0; nt < 4; nt++) {
            int row = bm + wm + mt * 16 + g;
            int col = bn + wn + nt * 8 + tg * 2;
#pragma unroll
            for (int half_i = 0; half_i < 2; half_i++) {
                int m = row + half_i * 8;
                float v0 = acc[mt][nt][half_i * 2 + 0];
                float v1 = acc[mt][nt][half_i * 2 + 1];
                if (EPI == 1) {
                    v0 = 0.5f * v0 * (1.f + erff(v0 * 0.70710678118f));
                    v1 = 0.5f * v1 * (1.f + erff(v1 * 0.70710678118f));
                }
                if (EPI == 2) { v0 = fmaxf(v0, 0.f); v1 = fmaxf(v1, 0.f); }
                if (EPI == 3) {
                    int bidx = m >> 11;
                    float al = AB[bidx * 2], be = AB[bidx * 2 + 1];
                    float2 rx = *reinterpret_cast<const float2*>(&R[(size_t)m * N + col]);
                    __half2 rfh = *reinterpret_cast<const __half2*>(&R2h[(size_t)m * N + col]);
                    float2 rf = __half22float2(rfh);
                    v0 = rx.x + al * rf.x + be * v0;
                    v1 = rx.y + al * rf.y + be * v1;
                }
                if (RESID) {
                    float2 r2 = *reinterpret_cast<const float2*>(&R[(size_t)m * N + col]);
                    v0 += r2.x; v1 += r2.y;
                }
                if (OUTH) {
                    __half2 hv = __floats2half2_rn(v0, v1);
                    *reinterpret_cast<__half2*>(&((__half*)Cv)[(size_t)m * N + col]) = hv;
                } else {
                    *reinterpret_cast<float2*>(&((float*)Cv)[(size_t)m * N + col]) =
                        make_float2(v0, v1);
                }
            }
        }
    }
}

template<int EPI, bool RESID, bool OUTH>
__global__ void __launch_bounds__(256, 2) gemmh(const __half* __restrict__ A,
                                                const __half* __restrict__ B,
                                                const float* __restrict__ R,
                                                void* __restrict__ C,
                                                int N, int K) {
    gemmh_body<EPI, RESID, OUTH>(A, B, R, C, N, K, blockIdx.y * 128, blockIdx.x * 128);
}

__global__ void __launch_bounds__(256, 2) gemmh_up_combine(const __half* __restrict__ A,
                                                           const __half* __restrict__ B,
                                                           const float* __restrict__ x1,
                                                           const __half* __restrict__ ffnh,
                                                           const float* __restrict__ ab,
                                                           float* __restrict__ out) {
    gemmh_body<3, false, false>(A, B, x1, out, DMODEL, BOT,
                                blockIdx.y * 128, blockIdx.x * 128, ffnh, ab);
}

__global__ void __launch_bounds__(256, 2) gemmh_qkv(const __half* __restrict__ A,
                                                    const __half* __restrict__ B0,
                                                    const __half* __restrict__ B1,
                                                    const __half* __restrict__ B2,
                                                    __half* __restrict__ C0,
                                                    __half* __restrict__ C1,
                                                    __half* __restrict__ C2) {
    const int sel = blockIdx.x >> 3;
    const __half* B = (sel == 0) ? B0 : (sel == 1) ? B1 : B2;
    __half* C = (sel == 0) ? C0 : (sel == 1) ? C1 : C2;
    gemmh_body<0, false, true>(A, B, nullptr, C, DMODEL, DMODEL,
                               blockIdx.y * 128, (blockIdx.x & 7) * 128);
}

__global__ void __launch_bounds__(256, 2) gemmh_w1_down(const __half* __restrict__ A,
                                                        const __half* __restrict__ w1,
                                                        const __half* __restrict__ down,
                                                        __half* __restrict__ hid,
                                                        __half* __restrict__ ph) {
    if (blockIdx.x < 32) {
        gemmh_body<1, false, true>(A, w1, nullptr, hid, DFF, DMODEL,
                                   blockIdx.y * 128, blockIdx.x * 128);
    } else {
        gemmh_body<2, false, true>(A, down, nullptr, ph, BOT, DMODEL,
                                   blockIdx.y * 128, (blockIdx.x - 32) * 128);
    }
}

// ============ fp16 mma.sync flash attention (causal, K-tile 128, double-buffered) ============
#define QSTR 72
#define AQ_HALVES (128*QSTR)
#define AT_HALVES (128*QSTR)
#define ATT_SMEM_BYTES ((AQ_HALVES + 4*AT_HALVES) * 2)

__global__ void __launch_bounds__(256) attn_mma_kernel(const __half* __restrict__ Q,
                                                       const __half* __restrict__ K,
                                                       const __half* __restrict__ V,
                                                       __half* __restrict__ O) {
    extern __shared__ __half asmem[];
    const uint32_t sbase = smem_u32(asmem);
    const uint32_t sQ = sbase;

    const int qt = (int)(gridDim.x - 1 - blockIdx.x);
    const int h = blockIdx.y;
    const int b = blockIdx.z;
    const int tid = threadIdx.x;
    const int w = tid >> 5;
    const int lane = tid & 31;
    const int g = lane >> 2;
    const int tg = lane & 3;
    const int sub = lane >> 3;
    const int rin = lane & 7;
    const size_t headoff = (size_t)h * DHEAD;

    // load K/V tile kb (128 keys x 64 dh) into buffer buf
    auto issue = [&](int kb, int buf) {
        const uint32_t kb_base = sbase + (AQ_HALVES + buf * AT_HALVES) * 2;
        const uint32_t vb_base = sbase + (AQ_HALVES + (2 + buf) * AT_HALVES) * 2;
#pragma unroll
        for (int i = 0; i < 4; i++) {
            int e = tid + i * 256;
            int r = e >> 3, c8 = e & 7;
            size_t gb = ((size_t)(b * TSEQ + kb * 128 + r)) * DMODEL + headoff + c8 * 8;
            uint32_t soff = (uint32_t)(r * QSTR + c8 * 8) * 2;
            cp16(kb_base + soff, &K[gb]);
            cp16(vb_base + soff, &V[gb]);
        }
    };

    issue(0, 0);
#pragma unroll
    for (int i = 0; i < 4; i++) {
        int e = tid + i * 256;
        int r = e >> 3, c8 = e & 7;
        size_t gb = ((size_t)(b * TSEQ + qt * 128 + r)) * DMODEL + headoff + c8 * 8;
        cp16(sQ + (uint32_t)(r * QSTR + c8 * 8) * 2, &Q[gb]);
    }
    CP_COMMIT();
    CP_WAIT0();
    __syncthreads();

    uint32_t qf[4][4];
#pragma unroll
    for (int ks = 0; ks < 4; ks++) {
        int row = w * 16 + rin + (sub & 1) * 8;
        int col = ks * 16 + (sub >> 1) * 8;
        ldsm4(qf[ks][0], qf[ks][1], qf[ks][2], qf[ks][3],
              sQ + (uint32_t)(row * QSTR + col) * 2);
    }

    float o[8][4];
#pragma unroll
    for (int nt = 0; nt < 8; nt++)
#pragma unroll
        for (int l = 0; l < 4; l++) o[nt][l] = 0.f;
    float m0 = -1e30f, m1 = -1e30f, l0 = 0.f, l1 = 0.f;

    const int rowg = qt * 128 + w * 16 + g;

    for (int kb = 0; kb <= qt; kb++) {
        CP_WAIT0();
        __syncthreads();
        if (kb < qt) {
            issue(kb + 1, (kb + 1) & 1);
            CP_COMMIT();
        }

        const uint32_t sK = sbase + (AQ_HALVES + (kb & 1) * AT_HALVES) * 2;
        const uint32_t sV = sbase + (AQ_HALVES + (2 + (kb & 1)) * AT_HALVES) * 2;

        // ---- S = Q K^T over 128 keys ----
        float s[16][4];
#pragma unroll
        for (int nt = 0; nt < 16; nt++)
#pragma unroll
            for (int l = 0; l < 4; l++) s[nt][l] = 0.f;
#pragma unroll
        for (int ks = 0; ks < 4; ks++) {
            uint32_t bf[16][2];
#pragma unroll
            for (int p = 0; p < 8; p++) {
                int nrow = (2 * p + (sub >> 1)) * 8 + rin;
                int ncol = ks * 16 + (sub & 1) * 8;
                ldsm4(bf[2 * p][0], bf[2 * p][1], bf[2 * p + 1][0], bf[2 * p + 1][1],
                      sK + (uint32_t)(nrow * QSTR + ncol) * 2);
            }
#pragma unroll
            for (int nt = 0; nt < 16; nt++)
                mma_f16(s[nt][0], s[nt][1], s[nt][2], s[nt][3],
                        qf[ks][0], qf[ks][1], qf[ks][2], qf[ks][3],
                        bf[nt][0], bf[nt][1]);
        }

        // ---- causal mask (diagonal tile only) ----
        if (kb == qt) {
#pragma unroll
            for (int nt = 0; nt < 16; nt++) {
                int c = kb * 128 + nt * 8 + 2 * tg;
                if (c > rowg) s[nt][0] = -1e30f;
                if (c + 1 > rowg) s[nt][1] = -1e30f;
                if (c > rowg + 8) s[nt][2] = -1e30f;
                if (c + 1 > rowg + 8) s[nt][3] = -1e30f;
            }
        }

        // ---- online softmax; P packs into m16n8k16 A-fragments ----
        float mx0 = -1e30f, mx1 = -1e30f;
#pragma unroll
        for (int nt = 0; nt < 16; nt++) {
            mx0 = fmaxf(mx0, fmaxf(s[nt][0], s[nt][1]));
            mx1 = fmaxf(mx1, fmaxf(s[nt][2], s[nt][3]));
        }
        mx0 = fmaxf(mx0, __shfl_xor_sync(0xffffffffu, mx0, 1));
        mx0 = fmaxf(mx0, __shfl_xor_sync(0xffffffffu, mx0, 2));
        mx1 = fmaxf(mx1, __shfl_xor_sync(0xffffffffu, mx1, 1));
        mx1 = fmaxf(mx1, __shfl_xor_sync(0xffffffffu, mx1, 2));
        float nm0 = fmaxf(m0, mx0), nm1 = fmaxf(m1, mx1);
        float sc0 = __expf(m0 - nm0), sc1 = __expf(m1 - nm1);
        m0 = nm0; m1 = nm1;
        float sum0 = 0.f, sum1 = 0.f;
        uint32_t pf[8][4];
#pragma unroll
        for (int nt = 0; nt < 16; nt++) {
            float p0 = __expf(s[nt][0] - nm0);
            float p1 = __expf(s[nt][1] - nm0);
            float p2 = __expf(s[nt][2] - nm1);
            float p3 = __expf(s[nt][3] - nm1);
            sum0 += p0 + p1; sum1 += p2 + p3;
            int ks = nt >> 1;
            if ((nt & 1) == 0) {
                pf[ks][0] = packh2(p0, p1);
                pf[ks][1] = packh2(p2, p3);
            } else {
                pf[ks][2] = packh2(p0, p1);
                pf[ks][3] = packh2(p2, p3);
            }
        }
        sum0 += __shfl_xor_sync(0xffffffffu, sum0, 1);
        sum0 += __shfl_xor_sync(0xffffffffu, sum0, 2);
        sum1 += __shfl_xor_sync(0xffffffffu, sum1, 1);
        sum1 += __shfl_xor_sync(0xffffffffu, sum1, 2);
        l0 = l0 * sc0 + sum0;
        l1 = l1 * sc1 + sum1;
#pragma unroll
        for (int nt = 0; nt < 8; nt++) {
            o[nt][0] *= sc0; o[nt][1] *= sc0;
            o[nt][2] *= sc1; o[nt][3] *= sc1;
        }

        // ---- O += P V (128 keys = 8 k-chunks) ----
#pragma unroll
        for (int ks = 0; ks < 8; ks++) {
            uint32_t vf[8][2];
#pragma unroll
            for (int np = 0; np < 4; np++) {
                int krow = ks * 16 + ((sub & 1) * 8) + rin;
                int ncol = np * 16 + (sub >> 1) * 8;
                ldsm4t(vf[2 * np][0], vf[2 * np][1], vf[2 * np + 1][0], vf[2 * np + 1][1],
                       sV + (uint32_t)(krow * QSTR + ncol) * 2);
            }
#pragma unroll
            for (int nt = 0; nt < 8; nt++)
                mma_f16(o[nt][0], o[nt][1], o[nt][2], o[nt][3],
                        pf[ks][0], pf[ks][1], pf[ks][2], pf[ks][3],
                        vf[nt][0], vf[nt][1]);
        }
    }

    float il0 = 1.f / l0, il1 = 1.f / l1;
    const size_t rg = (size_t)(b * TSEQ + qt * 128 + w * 16 + g);
#pragma unroll
    for (int nt = 0; nt < 8; nt++) {
        size_t col = headoff + nt * 8 + 2 * tg;
        *reinterpret_cast<__half2*>(&O[rg * DMODEL + col]) =
            __floats2half2_rn(o[nt][0] * il0, o[nt][1] * il0);
        *reinterpret_cast<__half2*>(&O[(rg + 8) * DMODEL + col]) =
            __floats2half2_rn(o[nt][2] * il1, o[nt][3] * il1);
    }
}

// ---------------- RMSNorm (fp32 in, fp16 out) ----------------
__global__ void __launch_bounds__(256) rmsnorm_kernel(const float* __restrict__ x,
                                                      const float* __restrict__ w,
                                                      __half* __restrict__ out) {
    const int row = blockIdx.x;
    const float* xr = x + (size_t)row * DMODEL;
    __half* orow = out + (size_t)row * DMODEL;
    const int tid = threadIdx.x;

    float vals[4];
    float local = 0.f;
#pragma unroll
    for (int i = 0; i < 4; i++) {
        float v = xr[tid + i * 256];
        vals[i] = v;
        local += v * v;
    }
    for (int off = 16; off; off >>= 1) local += __shfl_xor_sync(0xffffffffu, local, off);
    __shared__ float red[8];
    __shared__ float rinv_s;
    int warp = tid >> 5, lane = tid & 31;
    if (lane == 0) red[warp] = local;
    __syncthreads();
    if (tid == 0) {
        float tot = 0.f;
#pragma unroll
        for (int i = 0; i < 8; i++) tot += red[i];
        rinv_s = rsqrtf(tot * (1.0f / DMODEL) + EPS);
    }
    __syncthreads();
    float rinv = rinv_s;
#pragma unroll
    for (int i = 0; i < 4; i++) {
        int c = tid + i * 256;
        orow[c] = __float2half_rn(vals[i] * rinv * w[c]);
    }
}

// ---------------- RoPE: fp16 in-place rotate, half2-vectorized (q scaled by 1/8) ----------------
__global__ void rope_kernel(__half* __restrict__ qh, __half* __restrict__ kh) {
    int idx = blockIdx.x * blockDim.x + threadIdx.x;
    if (idx >= BT * 256) return;
    int row = idx >> 8;
    int p = idx & 255;
    int h = p >> 4;
    int i2 = p & 15;
    int t = row & (TSEQ - 1);
    float inv0 = expf(-((float)(4 * i2) / 64.f) * 9.210340371976184f);
    float inv1 = expf(-((float)(4 * i2 + 2) / 64.f) * 9.210340371976184f);
    float s0, c0, s1, c1;
    sincosf((float)t * inv0, &s0, &c0);
    sincosf((float)t * inv1, &s1, &c1);
    size_t base = (size_t)row * DMODEL + h * DHEAD + 2 * i2;

    float2 qa = __half22float2(*reinterpret_cast<__half2*>(&qh[base]));
    float2 qb = __half22float2(*reinterpret_cast<__half2*>(&qh[base + 32]));
    *reinterpret_cast<__half2*>(&qh[base]) =
        __floats2half2_rn((qa.x * c0 - qb.x * s0) * 0.125f, (qa.y * c1 - qb.y * s1) * 0.125f);
    *reinterpret_cast<__half2*>(&qh[base + 32]) =
        __floats2half2_rn((qb.x * c0 + qa.x * s0) * 0.125f, (qb.y * c1 + qa.y * s1) * 0.125f);

    float2 ka = __half22float2(*reinterpret_cast<__half2*>(&kh[base]));
    float2 kb = __half22float2(*reinterpret_cast<__half2*>(&kh[base + 32]));
    *reinterpret_cast<__half2*>(&kh[base]) =
        __floats2half2_rn(ka.x * c0 - kb.x * s0, ka.y * c1 - kb.y * s1);
    *reinterpret_cast<__half2*>(&kh[base + 32]) =
        __floats2half2_rn(kb.x * c0 + ka.x * s0, kb.y * c1 + ka.y * s1);
}

// ---------------- mean over tokens pass 1 (fp16 input, half2-vectorized) ----------------
__global__ void mean_pass1(const __half* __restrict__ n2, float* __restrict__ gpart) {
    int b = blockIdx.y;
    int tc = blockIdx.z;
    int d2 = blockIdx.x * 256 + threadIdx.x;
    const __half2* p = reinterpret_cast<const __half2*>(
        n2 + (size_t)b * TSEQ * DMODEL + (size_t)tc * 256 * DMODEL) + d2;
    float sx = 0.f, sy = 0.f;
    for (int t = 0; t < 256; t++) {
        float2 v = __half22float2(p[(size_t)t * (DMODEL / 2)]);
        sx += v.x; sy += v.y;
    }
    float2* gp = reinterpret_cast<float2*>(gpart + ((size_t)tc * BATCH + b) * DMODEL);
    gp[d2] = make_float2(sx, sy);
}

// ---------------- fused mean pass 2 + alpha/beta MLP (single block) ----------------
__global__ void __launch_bounds__(256) mean2_ab_kernel(const float* __restrict__ gpart,
                                                       const float* __restrict__ fc1,
                                                       const float* __restrict__ fc2,
                                                       float* __restrict__ ab) {
    __shared__ float gv[BATCH * DMODEL];
    __shared__ float hs[BATCH][ABH];
    const int tid = threadIdx.x;
    for (int i = tid; i < BATCH * DMODEL; i += 256) {
        float s = 0.f;
#pragma unroll
        for (int tc = 0; tc < 8; tc++) s += gpart[(size_t)tc * BATCH * DMODEL + i];
        gv[i] = s * (1.f / TSEQ);
    }
    __syncthreads();
    if (tid < 128) {
        int b = tid >> 5, hh = tid & 31;
        float s = 0.f;
        for (int d = 0; d < DMODEL; d++) s += gv[b * DMODEL + d] * fc1[hh * DMODEL + d];
        hs[b][hh] = fmaxf(s, 0.f);
    }
    __syncthreads();
    if (tid < 2 * BATCH) {
        int bb = tid >> 1, o = tid & 1;
        float s2 = 0.f;
#pragma unroll
        for (int j = 0; j < ABH; j++) s2 += hs[bb][j] * fc2[o * ABH + j];
        ab[bb * 2 + o] = 1.f / (1.f + expf(-s2));
    }
}

// ---------------- launch ----------------
extern "C" void kernel_launch(void* const* d_in, const int* in_sizes, int n_in,
                              void* d_out, int out_size) {
    const float* x       = (const float*)d_in[0];
    const float* norm1_w = (const float*)d_in[2];
    const float* Wq      = (const float*)d_in[3];
    const float* Wk      = (const float*)d_in[4];
    const float* Wv      = (const float*)d_in[5];
    const float* Wo      = (const float*)d_in[6];
    const float* norm2_w = (const float*)d_in[7];
    const float* w1      = (const float*)d_in[8];
    const float* w2      = (const float*)d_in[9];
    const float* fc1     = (const float*)d_in[10];
    const float* fc2     = (const float*)d_in[11];
    const float* down    = (const float*)d_in[12];
    const float* up      = (const float*)d_in[13];
    float* out = (float*)d_out;

    __half *xn1h, *qh, *kh, *vh, *atth, *n2h, *hidh, *ffnh, *phh, *hWall;
    float *x1, *gpart, *ab;
    cudaGetSymbolAddress((void**)&xn1h,  g_xn1h);
    cudaGetSymbolAddress((void**)&qh,    g_qh);
    cudaGetSymbolAddress((void**)&kh,    g_kh);
    cudaGetSymbolAddress((void**)&vh,    g_vh);
    cudaGetSymbolAddress((void**)&atth,  g_atth);
    cudaGetSymbolAddress((void**)&x1,    g_x1);
    cudaGetSymbolAddress((void**)&n2h,   g_n2h);
    cudaGetSymbolAddress((void**)&hidh,  g_hidh);
    cudaGetSymbolAddress((void**)&ffnh,  g_ffnh);
    cudaGetSymbolAddress((void**)&phh,   g_phh);
    cudaGetSymbolAddress((void**)&gpart, g_gpart);
    cudaGetSymbolAddress((void**)&ab,    g_ab);
    cudaGetSymbolAddress((void**)&hWall, g_hWall);

    const __half* hWq   = hWall;
    const __half* hWk   = hWall + 1048576;
    const __half* hWv   = hWall + 2097152;
    const __half* hWo   = hWall + 3145728;
    const __half* hw1   = hWall + 4194304;
    const __half* hw2   = hWall + 8388608;
    const __half* hdown = hWall + 12582912;
    const __half* hup   = hWall + 12845056;

    static bool attr_set = false;
    if (!attr_set) {
        cudaFuncSetAttribute((const void*)attn_mma_kernel,
                             cudaFuncAttributeMaxDynamicSharedMemorySize, ATT_SMEM_BYTES);
        cudaFuncSetAttribute((const void*)gemmh<0, true, false>,
                             cudaFuncAttributeMaxDynamicSharedMemorySize, GEMMH_SMEM);
        cudaFuncSetAttribute((const void*)gemmh<0, false, true>,
                             cudaFuncAttributeMaxDynamicSharedMemorySize, GEMMH_SMEM);
        cudaFuncSetAttribute((const void*)gemmh_qkv,
                             cudaFuncAttributeMaxDynamicSharedMemorySize, GEMMH_SMEM);
        cudaFuncSetAttribute((const void*)gemmh_up_combine,
                             cudaFuncAttributeMaxDynamicSharedMemorySize, GEMMH_SMEM);
        cudaFuncSetAttribute((const void*)gemmh_w1_down,
                             cudaFuncAttributeMaxDynamicSharedMemorySize, GEMMH_SMEM);
        attr_set = true;
    }

    // 0. convert all weights to fp16
    SrcPtrs sp;
    sp.p[0] = (const float4*)Wq;  sp.p[1] = (const float4*)Wk;
    sp.p[2] = (const float4*)Wv;  sp.p[3] = (const float4*)Wo;
    sp.p[4] = (const float4*)w1;  sp.p[5] = (const float4*)w2;
    sp.p[6] = (const float4*)down; sp.p[7] = (const float4*)up;
    f2h_all_kernel<<<3200, 256>>>(sp, (uint2*)hWall);

    // 1. norm1 (fp16 out)
    rmsnorm_kernel<<<BT, 256>>>(x, norm1_w, xn1h);
    // 2. fused QKV (all fp16 out)
    gemmh_qkv<<<dim3(24, BT / 128), 256, GEMMH_SMEM>>>(xn1h, hWq, hWk, hWv, qh, kh, vh);
    // 3. RoPE
    rope_kernel<<<(BT * 256 + 255) / 256, 256>>>(qh, kh);
    // 4. attention (fp16 mma flash, K-tile 128)
    attn_mma_kernel<<<dim3(TSEQ / 128, NHEADS, BATCH), 256, ATT_SMEM_BYTES>>>(qh, kh, vh, atth);
    // 5. output proj + residual (fp32 out)
    gemmh<0, true, false><<<dim3(DMODEL / 128, BT / 128), 256, GEMMH_SMEM>>>(atth, hWo, x, x1, DMODEL, DMODEL);
    // 6. norm2 (fp16 out)
    rmsnorm_kernel<<<BT, 256>>>(x1, norm2_w, n2h);
    // 7. alpha/beta gate
    mean_pass1<<<dim3(DMODEL / 512, BATCH, 8), 256>>>(n2h, gpart);
    mean2_ab_kernel<<<1, 256>>>(gpart, fc1, fc2, ab);
    // 8. merged w1(+GELU) and down(+ReLU)
    gemmh_w1_down<<<dim3(34, BT / 128), 256, GEMMH_SMEM>>>(n2h, hw1, hdown, hidh, phh);
    // 9. w2 (fp16 ffn out)
    gemmh<0, false, true><<<dim3(DMODEL / 128, BT / 128), 256, GEMMH_SMEM>>>(hidh, hw2, nullptr, ffnh, DMODEL, DFF);
    // 10. up-proj + fused combine -> out
    gemmh_up_combine<<<dim3(DMODEL / 128, BT / 128), 256, GEMMH_SMEM>>>(phh, hup, x1, ffnh, ab, out);
}

// round 16
// speedup vs baseline: 1.0027x; 1.0027x over previous
#include <cuda_runtime.h>
#include <cuda_fp16.h>
#include <cuda_bf16.h>
#include <cstdint>
#include <math.h>

// Problem sizes (fixed)
#define BATCH 4
#define TSEQ 2048
#define BT (BATCH*TSEQ)       // 8192
#define DMODEL 1024
#define NHEADS 16
#define DHEAD 64
#define DFF 4096
#define BOT 256
#define ABH 32
#define EPS 1e-6f

// -------- static scratch (allocation-free contract) --------
__device__ __align__(256) __half g_xn1h[BT*DMODEL];
__device__ __align__(256) __half g_qh[BT*DMODEL];
__device__ __align__(256) __half g_kh[BT*DMODEL];
__device__ __align__(256) __half g_vh[BT*DMODEL];
__device__ __align__(256) __half g_atth[BT*DMODEL];
__device__ float g_x1[BT*DMODEL];
__device__ __align__(256) __half g_n2h[BT*DMODEL];
__device__ __align__(256) __half g_hidh[BT*DFF];
__device__ __align__(256) __half g_ffnh[BT*DMODEL];
__device__ __align__(256) __half g_phh[BT*BOT];
__device__ float g_gpart[8*BATCH*DMODEL];
__device__ float g_ab[2*BATCH];
// single fp16 weight arena (converted per call)
#define HW_TOTAL_ELEMS 13107200
__device__ __align__(256) __half g_hWall[HW_TOTAL_ELEMS];

// ---------------- helpers ----------------
__device__ __forceinline__ uint32_t smem_u32(const void* p) {
    uint32_t a;
    asm("{ .reg .u64 t; cvta.to.shared.u64 t, %1; cvt.u32.u64 %0, t; }" : "=r"(a) : "l"(p));
    return a;
}
__device__ __forceinline__ void cp16(uint32_t daddr, const void* gptr) {
    asm volatile("cp.async.cg.shared.global [%0], [%1], 16;" :: "r"(daddr), "l"(gptr) : "memory");
}
#define CP_COMMIT() asm volatile("cp.async.commit_group;" ::: "memory")
#define CP_WAIT0()  asm volatile("cp.async.wait_group 0;" ::: "memory")

__device__ __forceinline__ void mma_f16(float& c0, float& c1, float& c2, float& c3,
                                        uint32_t a0, uint32_t a1, uint32_t a2, uint32_t a3,
                                        uint32_t b0, uint32_t b1) {
    asm volatile(
        "mma.sync.aligned.m16n8k16.row.col.f32.f16.f16.f32 "
        "{%0,%1,%2,%3}, {%4,%5,%6,%7}, {%8,%9}, {%0,%1,%2,%3};"
        : "+f"(c0), "+f"(c1), "+f"(c2), "+f"(c3)
        : "r"(a0), "r"(a1), "r"(a2), "r"(a3), "r"(b0), "r"(b1));
}
__device__ __forceinline__ void ldsm4(uint32_t& r0, uint32_t& r1, uint32_t& r2, uint32_t& r3,
                                      uint32_t a) {
    asm volatile("ldmatrix.sync.aligned.m8n8.x4.shared.b16 {%0,%1,%2,%3}, [%4];"
                 : "=r"(r0), "=r"(r1), "=r"(r2), "=r"(r3) : "r"(a));
}
__device__ __forceinline__ void ldsm4t(uint32_t& r0, uint32_t& r1, uint32_t& r2, uint32_t& r3,
                                       uint32_t a) {
    asm volatile("ldmatrix.sync.aligned.m8n8.x4.trans.shared.b16 {%0,%1,%2,%3}, [%4];"
                 : "=r"(r0), "=r"(r1), "=r"(r2), "=r"(r3) : "r"(a));
}
__device__ __forceinline__ uint32_t packh2(float a, float b) {
    __half2 h = __floats2half2_rn(a, b);
    return *reinterpret_cast<uint32_t*>(&h);
}

// ---------------- fused fp32 -> fp16 converter for all weights ----------------
struct SrcPtrs { const float4* p[8]; };

__global__ void __launch_bounds__(256) f2h_all_kernel(SrcPtrs sp, uint2* __restrict__ dst) {
    const int t = blockIdx.x * 256 + threadIdx.x;
#pragma unroll
    for (int j = 0; j < 4; j++) {
        int idx = t + j * 819200;
        int seg, base;
        if (idx < 1048576)      { seg = idx >> 18;                    base = seg << 18; }
        else if (idx < 3145728) { seg = 4 + ((idx - 1048576) >> 20);  base = 1048576 + ((seg - 4) << 20); }
        else                    { seg = 6 + ((idx - 3145728) >> 16);  base = 3145728 + ((seg - 6) << 16); }
        float4 v = sp.p[seg][idx - base];
        __half2 lo = __floats2half2_rn(v.x, v.y);
        __half2 hi = __floats2half2_rn(v.z, v.w);
        dst[idx] = make_uint2(*(uint32_t*)&lo, *(uint32_t*)&hi);
    }
}

// ============ fp16 mma.sync GEMM: C = A[M,K] @ B[N,K]^T (+epilogue) ============
// CTA 128x128, BK=64, 2-stage double buffer, 2 CTAs/SM, 1 sync per chunk.
// EPI: 0 none, 1 GELU, 2 ReLU, 3 combine, 4 rope-q (scale 1/8), 5 rope-k.
#define SMSH 72
#define HMAT_BYTES (128 * SMSH * 2)
#define HSTAGE_BYTES (2 * HMAT_BYTES)
#define GEMMH_SMEM (2 * HSTAGE_BYTES)
#define RSTR 136      // rope staging stride (halves)

template<int EPI, bool RESID, bool OUTH>
__device__ __forceinline__ void gemmh_body(const __half* __restrict__ A,
                                           const __half* __restrict__ B,
                                           const float* __restrict__ R,
                                           void* __restrict__ Cv,
                                           int N, int K, int bm, int bn,
                                           const __half* __restrict__ R2h = nullptr,
                                           const float* __restrict__ AB = nullptr) {
    extern __shared__ __half hsmem[];
    const uint32_t sbase = smem_u32(hsmem);

    const int tid = threadIdx.x;
    const int warp = tid >> 5;
    const int lane = tid & 31;
    const int g = lane >> 2;
    const int tg = lane & 3;
    const int sub = lane >> 3;
    const int rin = lane & 7;
    const int wm = (warp & 1) * 64;
    const int wn = (warp >> 1) * 32;

    const int NC = K >> 6;

    auto issue = [&](int kc) {
        const uint32_t ab = sbase + (kc & 1) * HSTAGE_BYTES;
        const uint32_t bb = ab + HMAT_BYTES;
        const int k0 = kc << 6;
#pragma unroll
        for (int i = 0; i < 4; i++) {
            int e = tid + i * 256;
            int r = e >> 3, q8 = e & 7;
            uint32_t soff = (uint32_t)(r * SMSH + q8 * 8) * 2;
            cp16(ab + soff, &A[(size_t)(bm + r) * K + k0 + q8 * 8]);
            cp16(bb + soff, &B[(size_t)(bn + r) * K + k0 + q8 * 8]);
        }
    };

    float acc[4][4][4];
#pragma unroll
    for (int i = 0; i < 4; i++)
#pragma unroll
        for (int j = 0; j < 4; j++)
#pragma unroll
            for (int l = 0; l < 4; l++) acc[i][j][l] = 0.f;

    issue(0); CP_COMMIT();

    for (int kc = 0; kc < NC; kc++) {
        CP_WAIT0();
        __syncthreads();
        if (kc + 1 < NC) {
            issue(kc + 1);
            CP_COMMIT();
        }

        const uint32_t sA = sbase + (kc & 1) * HSTAGE_BYTES;
        const uint32_t sB = sA + HMAT_BYTES;

#pragma unroll
        for (int ks = 0; ks < 4; ks++) {
            uint32_t af[4][4], bf[4][2];
#pragma unroll
            for (int mt = 0; mt < 4; mt++) {
                int row = wm + mt * 16 + rin + (sub & 1) * 8;
                int col = ks * 16 + (sub >> 1) * 8;
                ldsm4(af[mt][0], af[mt][1], af[mt][2], af[mt][3],
                      sA + (uint32_t)(row * SMSH + col) * 2);
            }
#pragma unroll
            for (int p = 0; p < 2; p++) {
                int nrow = wn + (2 * p + (sub >> 1)) * 8 + rin;
                int ncol = ks * 16 + (sub & 1) * 8;
                ldsm4(bf[2 * p][0], bf[2 * p][1], bf[2 * p + 1][0], bf[2 * p + 1][1],
                      sB + (uint32_t)(nrow * SMSH + ncol) * 2);
            }
#pragma unroll
            for (int mt = 0; mt < 4; mt++)
#pragma unroll
                for (int nt = 0; nt < 4; nt++)
                    mma_f16(acc[mt][nt][0], acc[mt][nt][1], acc[mt][nt][2], acc[mt][nt][3],
                            af[mt][0], af[mt][1], af[mt][2], af[mt][3],
                            bf[nt][0], bf[nt][1]);
        }
    }

    if (EPI == 4 || EPI == 5) {
        // ---- fused RoPE epilogue: stage tile in smem, rotate pairs, write ----
        __syncthreads();                     // all warps done reading stage bufs
#pragma unroll
        for (int mt = 0; mt < 4; mt++)
#pragma unroll
            for (int nt = 0; nt < 4; nt++)
#pragma unroll
                for (int half_i = 0; half_i < 2; half_i++) {
                    int rl = wm + mt * 16 + g + half_i * 8;
                    int cl = wn + nt * 8 + tg * 2;
                    *reinterpret_cast<__half2*>(&hsmem[rl * RSTR + cl]) =
                        __floats2half2_rn(acc[mt][nt][half_i * 2 + 0],
                                          acc[mt][nt][half_i * 2 + 1]);
                }
        __syncthreads();
        const float scale = (EPI == 4) ? 0.125f : 1.0f;
        __half* Ch = (__half*)Cv;
#pragma unroll
        for (int j = 0; j < 32; j++) {
            int pidx = tid + j * 256;        // 0..8191
            int r = pidx >> 6;               // 0..127
            int p = pidx & 63;
            int head = p >> 5, i = p & 31;
            int c0 = head * 64 + i, c1 = c0 + 32;
            int m = bm + r;
            int t = m & (TSEQ - 1);
            float inv = __expf(-((float)(2 * i) / 64.f) * 9.210340371976184f);
            float sn, cs;
            sincosf((float)t * inv, &sn, &cs);
            float h0 = __half2float(hsmem[r * RSTR + c0]);
            float h1 = __half2float(hsmem[r * RSTR + c1]);
            Ch[(size_t)m * DMODEL + bn + c0] = __float2half_rn((h0 * cs - h1 * sn) * scale);
            Ch[(size_t)m * DMODEL + bn + c1] = __float2half_rn((h1 * cs + h0 * sn) * scale);
        }
        return;
    }

#pragma unroll
    for (int mt = 0; mt < 4; mt++) {
#pragma unroll
        for (int nt = 0; nt < 4; nt++) {
            int row = bm + wm + mt * 16 + g;
            int col = bn + wn + nt * 8 + tg * 2;
#pragma unroll
            for (int half_i = 0; half_i < 2; half_i++) {
                int m = row + half_i * 8;
                float v0 = acc[mt][nt][half_i * 2 + 0];
                float v1 = acc[mt][nt][half_i * 2 + 1];
                if (EPI == 1) {
                    v0 = 0.5f * v0 * (1.f + erff(v0 * 0.70710678118f));
                    v1 = 0.5f * v1 * (1.f + erff(v1 * 0.70710678118f));
                }
                if (EPI == 2) { v0 = fmaxf(v0, 0.f); v1 = fmaxf(v1, 0.f); }
                if (EPI == 3) {
                    int bidx = m >> 11;
                    float al = AB[bidx * 2], be = AB[bidx * 2 + 1];
                    float2 rx = *reinterpret_cast<const float2*>(&R[(size_t)m * N + col]);
                    __half2 rfh = *reinterpret_cast<const __half2*>(&R2h[(size_t)m * N + col]);
                    float2 rf = __half22float2(rfh);
                    v0 = rx.x + al * rf.x + be * v0;
                    v1 = rx.y + al * rf.y + be * v1;
                }
                if (RESID) {
                    float2 r2 = *reinterpret_cast<const float2*>(&R[(size_t)m * N + col]);
                    v0 += r2.x; v1 += r2.y;
                }
                if (OUTH) {
                    __half2 hv = __floats2half2_rn(v0, v1);
                    *reinterpret_cast<__half2*>(&((__half*)Cv)[(size_t)m * N + col]) = hv;
                } else {
                    *reinterpret_cast<float2*>(&((float*)Cv)[(size_t)m * N + col]) =
                        make_float2(v0, v1);
                }
            }
        }
    }
}

template<int EPI, bool RESID, bool OUTH>
__global__ void __launch_bounds__(256, 2) gemmh(const __half* __restrict__ A,
                                                const __half* __restrict__ B,
                                                const float* __restrict__ R,
                                                void* __restrict__ C,
                                                int N, int K) {
    gemmh_body<EPI, RESID, OUTH>(A, B, R, C, N, K, blockIdx.y * 128, blockIdx.x * 128);
}

__global__ void __launch_bounds__(256, 2) gemmh_up_combine(const __half* __restrict__ A,
                                                           const __half* __restrict__ B,
                                                           const float* __restrict__ x1,
                                                           const __half* __restrict__ ffnh,
                                                           const float* __restrict__ ab,
                                                           float* __restrict__ out) {
    gemmh_body<3, false, false>(A, B, x1, out, DMODEL, BOT,
                                blockIdx.y * 128, blockIdx.x * 128, ffnh, ab);
}

// fused QKV with epilogue RoPE on q (scaled) and k; v plain fp16
__global__ void __launch_bounds__(256, 2) gemmh_qkv(const __half* __restrict__ A,
                                                    const __half* __restrict__ B0,
                                                    const __half* __restrict__ B1,
                                                    const __half* __restrict__ B2,
                                                    __half* __restrict__ C0,
                                                    __half* __restrict__ C1,
                                                    __half* __restrict__ C2) {
    const int sel = blockIdx.x >> 3;
    const int bm = blockIdx.y * 128;
    const int bn = (blockIdx.x & 7) * 128;
    if (sel == 0) {
        gemmh_body<4, false, true>(A, B0, nullptr, C0, DMODEL, DMODEL, bm, bn);
    } else if (sel == 1) {
        gemmh_body<5, false, true>(A, B1, nullptr, C1, DMODEL, DMODEL, bm, bn);
    } else {
        gemmh_body<0, false, true>(A, B2, nullptr, C2, DMODEL, DMODEL, bm, bn);
    }
}

__global__ void __launch_bounds__(256, 2) gemmh_w1_down(const __half* __restrict__ A,
                                                        const __half* __restrict__ w1,
                                                        const __half* __restrict__ down,
                                                        __half* __restrict__ hid,
                                                        __half* __restrict__ ph) {
    if (blockIdx.x < 32) {
        gemmh_body<1, false, true>(A, w1, nullptr, hid, DFF, DMODEL,
                                   blockIdx.y * 128, blockIdx.x * 128);
    } else {
        gemmh_body<2, false, true>(A, down, nullptr, ph, BOT, DMODEL,
                                   blockIdx.y * 128, (blockIdx.x - 32) * 128);
    }
}

// ============ fp16 mma.sync flash attention (causal, K-tile 64, cp.async double-buffered) ============
#define QSTR 72
#define AQ_HALVES (128*QSTR)
#define AT_HALVES (64*QSTR)
#define ATT_SMEM_BYTES ((AQ_HALVES + 4*AT_HALVES) * 2)

__global__ void __launch_bounds__(256, 2) attn_mma_kernel(const __half* __restrict__ Q,
                                                          const __half* __restrict__ K,
                                                          const __half* __restrict__ V,
                                                          __half* __restrict__ O) {
    extern __shared__ __half asmem[];
    const uint32_t sbase = smem_u32(asmem);
    const uint32_t sQ = sbase;

    const int qt = (int)(gridDim.x - 1 - blockIdx.x);
    const int h = blockIdx.y;
    const int b = blockIdx.z;
    const int tid = threadIdx.x;
    const int w = tid >> 5;
    const int lane = tid & 31;
    const int g = lane >> 2;
    const int tg = lane & 3;
    const int sub = lane >> 3;
    const int rin = lane & 7;
    const size_t headoff = (size_t)h * DHEAD;

    auto issue = [&](int kb, int buf) {
        const uint32_t kb_base = sbase + (AQ_HALVES + buf * AT_HALVES) * 2;
        const uint32_t vb_base = sbase + (AQ_HALVES + (2 + buf) * AT_HALVES) * 2;
#pragma unroll
        for (int i = 0; i < 2; i++) {
            int e = tid + i * 256;
            int r = e >> 3, c8 = e & 7;
            size_t gb = ((size_t)(b * TSEQ + kb * 64 + r)) * DMODEL + headoff + c8 * 8;
            uint32_t soff = (uint32_t)(r * QSTR + c8 * 8) * 2;
            cp16(kb_base + soff, &K[gb]);
            cp16(vb_base + soff, &V[gb]);
        }
    };

    issue(0, 0);
#pragma unroll
    for (int i = 0; i < 4; i++) {
        int e = tid + i * 256;
        int r = e >> 3, c8 = e & 7;
        size_t gb = ((size_t)(b * TSEQ + qt * 128 + r)) * DMODEL + headoff + c8 * 8;
        cp16(sQ + (uint32_t)(r * QSTR + c8 * 8) * 2, &Q[gb]);
    }
    CP_COMMIT();
    CP_WAIT0();
    __syncthreads();

    uint32_t qf[4][4];
#pragma unroll
    for (int ks = 0; ks < 4; ks++) {
        int row = w * 16 + rin + (sub & 1) * 8;
        int col = ks * 16 + (sub >> 1) * 8;
        ldsm4(qf[ks][0], qf[ks][1], qf[ks][2], qf[ks][3],
              sQ + (uint32_t)(row * QSTR + col) * 2);
    }

    float o[8][4];
#pragma unroll
    for (int nt = 0; nt < 8; nt++)
#pragma unroll
        for (int l = 0; l < 4; l++) o[nt][l] = 0.f;
    float m0 = -1e30f, m1 = -1e30f, l0 = 0.f, l1 = 0.f;

    const int rowg = qt * 128 + w * 16 + g;
    const int kbmax = 2 * qt + 1;

    for (int kb = 0; kb <= kbmax; kb++) {
        CP_WAIT0();
        __syncthreads();
        if (kb < kbmax) {
            issue(kb + 1, (kb + 1) & 1);
            CP_COMMIT();
        }
        if (kb * 64 > qt * 128 + w * 16 + 15) continue;

        const uint32_t sK = sbase + (AQ_HALVES + (kb & 1) * AT_HALVES) * 2;
        const uint32_t sV = sbase + (AQ_HALVES + (2 + (kb & 1)) * AT_HALVES) * 2;

        float s[8][4];
#pragma unroll
        for (int nt = 0; nt < 8; nt++)
#pragma unroll
            for (int l = 0; l < 4; l++) s[nt][l] = 0.f;
#pragma unroll
        for (int ks = 0; ks < 4; ks++) {
            uint32_t bf[8][2];
#pragma unroll
            for (int p = 0; p < 4; p++) {
                int nrow = (2 * p + (sub >> 1)) * 8 + rin;
                int ncol = ks * 16 + (sub & 1) * 8;
                ldsm4(bf[2 * p][0], bf[2 * p][1], bf[2 * p + 1][0], bf[2 * p + 1][1],
                      sK + (uint32_t)(nrow * QSTR + ncol) * 2);
            }
#pragma unroll
            for (int nt = 0; nt < 8; nt++)
                mma_f16(s[nt][0], s[nt][1], s[nt][2], s[nt][3],
                        qf[ks][0], qf[ks][1], qf[ks][2], qf[ks][3],
                        bf[nt][0], bf[nt][1]);
        }

        if (kb * 64 + 63 > rowg) {
#pragma unroll
            for (int nt = 0; nt < 8; nt++) {
                int c = kb * 64 + nt * 8 + 2 * tg;
                if (c > rowg) s[nt][0] = -1e30f;
                if (c + 1 > rowg) s[nt][1] = -1e30f;
                if (c > rowg + 8) s[nt][2] = -1e30f;
                if (c + 1 > rowg + 8) s[nt][3] = -1e30f;
            }
        }

        float mx0 = -1e30f, mx1 = -1e30f;
#pragma unroll
        for (int nt = 0; nt < 8; nt++) {
            mx0 = fmaxf(mx0, fmaxf(s[nt][0], s[nt][1]));
            mx1 = fmaxf(mx1, fmaxf(s[nt][2], s[nt][3]));
        }
        mx0 = fmaxf(mx0, __shfl_xor_sync(0xffffffffu, mx0, 1));
        mx0 = fmaxf(mx0, __shfl_xor_sync(0xffffffffu, mx0, 2));
        mx1 = fmaxf(mx1, __shfl_xor_sync(0xffffffffu, mx1, 1));
        mx1 = fmaxf(mx1, __shfl_xor_sync(0xffffffffu, mx1, 2));
        float nm0 = fmaxf(m0, mx0), nm1 = fmaxf(m1, mx1);
        float sc0 = __expf(m0 - nm0), sc1 = __expf(m1 - nm1);
        m0 = nm0; m1 = nm1;
        float sum0 = 0.f, sum1 = 0.f;
        uint32_t pf[4][4];
#pragma unroll
        for (int nt = 0; nt < 8; nt++) {
            float p0 = __expf(s[nt][0] - nm0);
            float p1 = __expf(s[nt][1] - nm0);
            float p2 = __expf(s[nt][2] - nm1);
            float p3 = __expf(s[nt][3] - nm1);
            sum0 += p0 + p1; sum1 += p2 + p3;
            int ks = nt >> 1;
            if ((nt & 1) == 0) {
                pf[ks][0] = packh2(p0, p1);
                pf[ks][1] = packh2(p2, p3);
            } else {
                pf[ks][2] = packh2(p0, p1);
                pf[ks][3] = packh2(p2, p3);
            }
        }
        sum0 += __shfl_xor_sync(0xffffffffu, sum0, 1);
        sum0 += __shfl_xor_sync(0xffffffffu, sum0, 2);
        sum1 += __shfl_xor_sync(0xffffffffu, sum1, 1);
        sum1 += __shfl_xor_sync(0xffffffffu, sum1, 2);
        l0 = l0 * sc0 + sum0;
        l1 = l1 * sc1 + sum1;
#pragma unroll
        for (int nt = 0; nt < 8; nt++) {
            o[nt][0] *= sc0; o[nt][1] *= sc0;
            o[nt][2] *= sc1; o[nt][3] *= sc1;
        }

#pragma unroll
        for (int ks = 0; ks < 4; ks++) {
            uint32_t vf[8][2];
#pragma unroll
            for (int np = 0; np < 4; np++) {
                int krow = ks * 16 + ((sub & 1) * 8) + rin;
                int ncol = np * 16 + (sub >> 1) * 8;
                ldsm4t(vf[2 * np][0], vf[2 * np][1], vf[2 * np + 1][0], vf[2 * np + 1][1],
                       sV + (uint32_t)(krow * QSTR + ncol) * 2);
            }
#pragma unroll
            for (int nt = 0; nt < 8; nt++)
                mma_f16(o[nt][0], o[nt][1], o[nt][2], o[nt][3],
                        pf[ks][0], pf[ks][1], pf[ks][2], pf[ks][3],
                        vf[nt][0], vf[nt][1]);
        }
    }

    float il0 = 1.f / l0, il1 = 1.f / l1;
    const size_t rg = (size_t)(b * TSEQ + qt * 128 + w * 16 + g);
#pragma unroll
    for (int nt = 0; nt < 8; nt++) {
        size_t col = headoff + nt * 8 + 2 * tg;
        *reinterpret_cast<__half2*>(&O[rg * DMODEL + col]) =
            __floats2half2_rn(o[nt][0] * il0, o[nt][1] * il0);
        *reinterpret_cast<__half2*>(&O[(rg + 8) * DMODEL + col]) =
            __floats2half2_rn(o[nt][2] * il1, o[nt][3] * il1);
    }
}

// ---------------- RMSNorm (fp32 in, fp16 out) ----------------
__global__ void __launch_bounds__(256) rmsnorm_kernel(const float* __restrict__ x,
                                                      const float* __restrict__ w,
                                                      __half* __restrict__ out) {
    const int row = blockIdx.x;
    const float* xr = x + (size_t)row * DMODEL;
    __half* orow = out + (size_t)row * DMODEL;
    const int tid = threadIdx.x;

    float vals[4];
    float local = 0.f;
#pragma unroll
    for (int i = 0; i < 4; i++) {
        float v = xr[tid + i * 256];
        vals[i] = v;
        local += v * v;
    }
    for (int off = 16; off; off >>= 1) local += __shfl_xor_sync(0xffffffffu, local, off);
    __shared__ float red[8];
    __shared__ float rinv_s;
    int warp = tid >> 5, lane = tid & 31;
    if (lane == 0) red[warp] = local;
    __syncthreads();
    if (tid == 0) {
        float tot = 0.f;
#pragma unroll
        for (int i = 0; i < 8; i++) tot += red[i];
        rinv_s = rsqrtf(tot * (1.0f / DMODEL) + EPS);
    }
    __syncthreads();
    float rinv = rinv_s;
#pragma unroll
    for (int i = 0; i < 4; i++) {
        int c = tid + i * 256;
        orow[c] = __float2half_rn(vals[i] * rinv * w[c]);
    }
}

// ---------------- mean over tokens pass 1 (fp16 input, half2-vectorized) ----------------
__global__ void mean_pass1(const __half* __restrict__ n2, float* __restrict__ gpart) {
    int b = blockIdx.y;
    int tc = blockIdx.z;
    int d2 = blockIdx.x * 256 + threadIdx.x;
    const __half2* p = reinterpret_cast<const __half2*>(
        n2 + (size_t)b * TSEQ * DMODEL + (size_t)tc * 256 * DMODEL) + d2;
    float sx = 0.f, sy = 0.f;
    for (int t = 0; t < 256; t++) {
        float2 v = __half22float2(p[(size_t)t * (DMODEL / 2)]);
        sx += v.x; sy += v.y;
    }
    float2* gp = reinterpret_cast<float2*>(gpart + ((size_t)tc * BATCH + b) * DMODEL);
    gp[d2] = make_float2(sx, sy);
}

// ---------------- fused mean pass 2 + alpha/beta MLP (single block) ----------------
__global__ void __launch_bounds__(256) mean2_ab_kernel(const float* __restrict__ gpart,
                                                       const float* __restrict__ fc1,
                                                       const float* __restrict__ fc2,
                                                       float* __restrict__ ab) {
    __shared__ float gv[BATCH * DMODEL];
    __shared__ float hs[BATCH][ABH];
    const int tid = threadIdx.x;
    for (int i = tid; i < BATCH * DMODEL; i += 256) {
        float s = 0.f;
#pragma unroll
        for (int tc = 0; tc < 8; tc++) s += gpart[(size_t)tc * BATCH * DMODEL + i];
        gv[i] = s * (1.f / TSEQ);
    }
    __syncthreads();
    if (tid < 128) {
        int b = tid >> 5, hh = tid & 31;
        float s = 0.f;
        for (int d = 0; d < DMODEL; d++) s += gv[b * DMODEL + d] * fc1[hh * DMODEL + d];
        hs[b][hh] = fmaxf(s, 0.f);
    }
    __syncthreads();
    if (tid < 2 * BATCH) {
        int bb = tid >> 1, o = tid & 1;
        float s2 = 0.f;
#pragma unroll
        for (int j = 0; j < ABH; j++) s2 += hs[bb][j] * fc2[o * ABH + j];
        ab[bb * 2 + o] = 1.f / (1.f + expf(-s2));
    }
}

// ---------------- launch ----------------
extern "C" void kernel_launch(void* const* d_in, const int* in_sizes, int n_in,
                              void* d_out, int out_size) {
    const float* x       = (const float*)d_in[0];
    const float* norm1_w = (const float*)d_in[2];
    const float* Wq      = (const float*)d_in[3];
    const float* Wk      = (const float*)d_in[4];
    const float* Wv      = (const float*)d_in[5];
    const float* Wo      = (const float*)d_in[6];
    const float* norm2_w = (const float*)d_in[7];
    const float* w1      = (const float*)d_in[8];
    const float* w2      = (const float*)d_in[9];
    const float* fc1     = (const float*)d_in[10];
    const float* fc2     = (const float*)d_in[11];
    const float* down    = (const float*)d_in[12];
    const float* up      = (const float*)d_in[13];
    float* out = (float*)d_out;

    __half *xn1h, *qh, *kh, *vh, *atth, *n2h, *hidh, *ffnh, *phh, *hWall;
    float *x1, *gpart, *ab;
    cudaGetSymbolAddress((void**)&xn1h,  g_xn1h);
    cudaGetSymbolAddress((void**)&qh,    g_qh);
    cudaGetSymbolAddress((void**)&kh,    g_kh);
    cudaGetSymbolAddress((void**)&vh,    g_vh);
    cudaGetSymbolAddress((void**)&atth,  g_atth);
    cudaGetSymbolAddress((void**)&x1,    g_x1);
    cudaGetSymbolAddress((void**)&n2h,   g_n2h);
    cudaGetSymbolAddress((void**)&hidh,  g_hidh);
    cudaGetSymbolAddress((void**)&ffnh,  g_ffnh);
    cudaGetSymbolAddress((void**)&phh,   g_phh);
    cudaGetSymbolAddress((void**)&gpart, g_gpart);
    cudaGetSymbolAddress((void**)&ab,    g_ab);
    cudaGetSymbolAddress((void**)&hWall, g_hWall);

    const __half* hWq   = hWall;
    const __half* hWk   = hWall + 1048576;
    const __half* hWv   = hWall + 2097152;
    const __half* hWo   = hWall + 3145728;
    const __half* hw1   = hWall + 4194304;
    const __half* hw2   = hWall + 8388608;
    const __half* hdown = hWall + 12582912;
    const __half* hup   = hWall + 12845056;

    static bool attr_set = false;
    if (!attr_set) {
        cudaFuncSetAttribute((const void*)attn_mma_kernel,
                             cudaFuncAttributeMaxDynamicSharedMemorySize, ATT_SMEM_BYTES);
        cudaFuncSetAttribute((const void*)gemmh<0, true, false>,
                             cudaFuncAttributeMaxDynamicSharedMemorySize, GEMMH_SMEM);
        cudaFuncSetAttribute((const void*)gemmh<0, false, true>,
                             cudaFuncAttributeMaxDynamicSharedMemorySize, GEMMH_SMEM);
        cudaFuncSetAttribute((const void*)gemmh_qkv,
                             cudaFuncAttributeMaxDynamicSharedMemorySize, GEMMH_SMEM);
        cudaFuncSetAttribute((const void*)gemmh_up_combine,
                             cudaFuncAttributeMaxDynamicSharedMemorySize, GEMMH_SMEM);
        cudaFuncSetAttribute((const void*)gemmh_w1_down,
                             cudaFuncAttributeMaxDynamicSharedMemorySize, GEMMH_SMEM);
        attr_set = true;
    }

    // 0. convert all weights to fp16
    SrcPtrs sp;
    sp.p[0] = (const float4*)Wq;  sp.p[1] = (const float4*)Wk;
    sp.p[2] = (const float4*)Wv;  sp.p[3] = (const float4*)Wo;
    sp.p[4] = (const float4*)w1;  sp.p[5] = (const float4*)w2;
    sp.p[6] = (const float4*)down; sp.p[7] = (const float4*)up;
    f2h_all_kernel<<<3200, 256>>>(sp, (uint2*)hWall);

    // 1. norm1 (fp16 out)
    rmsnorm_kernel<<<BT, 256>>>(x, norm1_w, xn1h);
    // 2. fused QKV + epilogue RoPE (q scaled 1/8, k rotated, v plain)
    gemmh_qkv<<<dim3(24, BT / 128), 256, GEMMH_SMEM>>>(xn1h, hWq, hWk, hWv, qh, kh, vh);
    // 3. attention (fp16 mma flash, K-tile 64)
    attn_mma_kernel<<<dim3(TSEQ / 128, NHEADS, BATCH), 256, ATT_SMEM_BYTES>>>(qh, kh, vh, atth);
    // 4. output proj + residual (fp32 out)
    gemmh<0, true, false><<<dim3(DMODEL / 128, BT / 128), 256, GEMMH_SMEM>>>(atth, hWo, x, x1, DMODEL, DMODEL);
    // 5. norm2 (fp16 out)
    rmsnorm_kernel<<<BT, 256>>>(x1, norm2_w, n2h);
    // 6. alpha/beta gate
    mean_pass1<<<dim3(DMODEL / 512, BATCH, 8), 256>>>(n2h, gpart);
    mean2_ab_kernel<<<1, 256>>>(gpart, fc1, fc2, ab);
    // 7. merged w1(+GELU) and down(+ReLU)
    gemmh_w1_down<<<dim3(34, BT / 128), 256, GEMMH_SMEM>>>(n2h, hw1, hdown, hidh, phh);
    // 8. w2 (fp16 ffn out)
    gemmh<0, false, true><<<dim3(DMODEL / 128, BT / 128), 256, GEMMH_SMEM>>>(hidh, hw2, nullptr, ffnh, DMODEL, DFF);
    // 9. up-proj + fused combine -> out
    gemmh_up_combine<<<dim3(DMODEL / 128, BT / 128), 256, GEMMH_SMEM>>>(phh, hup, x1, ffnh, ab, out);
}

// round 17
// speedup vs baseline: 1.0125x; 1.0097x over previous
#include <cuda_runtime.h>
#include <cuda_fp16.h>
#include <cuda_bf16.h>
#include <cstdint>
#include <math.h>

// Problem sizes (fixed)
#define BATCH 4
#define TSEQ 2048
#define BT (BATCH*TSEQ)       // 8192
#define DMODEL 1024
#define NHEADS 16
#define DHEAD 64
#define DFF 4096
#define BOT 256
#define ABH 32
#define EPS 1e-6f

// -------- static scratch (allocation-free contract) --------
__device__ __align__(256) __half g_xn1h[BT*DMODEL];
__device__ __align__(256) __half g_qh[BT*DMODEL];
__device__ __align__(256) __half g_kh[BT*DMODEL];
__device__ __align__(256) __half g_vh[BT*DMODEL];
__device__ __align__(256) __half g_atth[BT*DMODEL];
__device__ float g_x1[BT*DMODEL];
__device__ __align__(256) __half g_n2h[BT*DMODEL];
__device__ __align__(256) __half g_hidh[BT*DFF];
__device__ __align__(256) __half g_ffnh[BT*DMODEL];
__device__ __align__(256) __half g_phh[BT*BOT];
__device__ float g_gpart[8*BATCH*DMODEL];
__device__ float g_ab[2*BATCH];
__device__ __align__(256) float2 g_rtbl[TSEQ*32];   // RoPE cos/sin table
// single fp16 weight arena (converted per call)
#define HW_TOTAL_ELEMS 13107200
__device__ __align__(256) __half g_hWall[HW_TOTAL_ELEMS];

// ---------------- helpers ----------------
__device__ __forceinline__ uint32_t smem_u32(const void* p) {
    uint32_t a;
    asm("{ .reg .u64 t; cvta.to.shared.u64 t, %1; cvt.u32.u64 %0, t; }" : "=r"(a) : "l"(p));
    return a;
}
__device__ __forceinline__ void cp16(uint32_t daddr, const void* gptr) {
    asm volatile("cp.async.cg.shared.global [%0], [%1], 16;" :: "r"(daddr), "l"(gptr) : "memory");
}
#define CP_COMMIT() asm volatile("cp.async.commit_group;" ::: "memory")
#define CP_WAIT0()  asm volatile("cp.async.wait_group 0;" ::: "memory")

__device__ __forceinline__ void mma_f16(float& c0, float& c1, float& c2, float& c3,
                                        uint32_t a0, uint32_t a1, uint32_t a2, uint32_t a3,
                                        uint32_t b0, uint32_t b1) {
    asm volatile(
        "mma.sync.aligned.m16n8k16.row.col.f32.f16.f16.f32 "
        "{%0,%1,%2,%3}, {%4,%5,%6,%7}, {%8,%9}, {%0,%1,%2,%3};"
        : "+f"(c0), "+f"(c1), "+f"(c2), "+f"(c3)
        : "r"(a0), "r"(a1), "r"(a2), "r"(a3), "r"(b0), "r"(b1));
}
__device__ __forceinline__ void ldsm4(uint32_t& r0, uint32_t& r1, uint32_t& r2, uint32_t& r3,
                                      uint32_t a) {
    asm volatile("ldmatrix.sync.aligned.m8n8.x4.shared.b16 {%0,%1,%2,%3}, [%4];"
                 : "=r"(r0), "=r"(r1), "=r"(r2), "=r"(r3) : "r"(a));
}
__device__ __forceinline__ void ldsm4t(uint32_t& r0, uint32_t& r1, uint32_t& r2, uint32_t& r3,
                                       uint32_t a) {
    asm volatile("ldmatrix.sync.aligned.m8n8.x4.trans.shared.b16 {%0,%1,%2,%3}, [%4];"
                 : "=r"(r0), "=r"(r1), "=r"(r2), "=r"(r3) : "r"(a));
}
__device__ __forceinline__ uint32_t packh2(float a, float b) {
    __half2 h = __floats2half2_rn(a, b);
    return *reinterpret_cast<uint32_t*>(&h);
}

// ---------------- RoPE table build: tbl[t*32+i] = (cos, sin)(t * 10000^(-2i/64)) ----------------
__global__ void __launch_bounds__(256) rope_tbl_kernel(float2* __restrict__ tbl) {
    int idx = blockIdx.x * 256 + threadIdx.x;    // 65536
    int t = idx >> 5, i = idx & 31;
    float inv = expf(-((float)(2 * i) / 64.f) * 9.210340371976184f);
    float s, c;
    sincosf((float)t * inv, &s, &c);
    tbl[idx] = make_float2(c, s);
}

// ---------------- fused fp32 -> fp16 converter for all weights ----------------
struct SrcPtrs { const float4* p[8]; };

__global__ void __launch_bounds__(256) f2h_all_kernel(SrcPtrs sp, uint2* __restrict__ dst) {
    const int t = blockIdx.x * 256 + threadIdx.x;
#pragma unroll
    for (int j = 0; j < 4; j++) {
        int idx = t + j * 819200;
        int seg, base;
        if (idx < 1048576)      { seg = idx >> 18;                    base = seg << 18; }
        else if (idx < 3145728) { seg = 4 + ((idx - 1048576) >> 20);  base = 1048576 + ((seg - 4) << 20); }
        else                    { seg = 6 + ((idx - 3145728) >> 16);  base = 3145728 + ((seg - 6) << 16); }
        float4 v = sp.p[seg][idx - base];
        __half2 lo = __floats2half2_rn(v.x, v.y);
        __half2 hi = __floats2half2_rn(v.z, v.w);
        dst[idx] = make_uint2(*(uint32_t*)&lo, *(uint32_t*)&hi);
    }
}

// ============ fp16 mma.sync GEMM: C = A[M,K] @ B[N,K]^T (+epilogue) ============
// CTA 128x128, BK=64, 2-stage double buffer, 2 CTAs/SM, 1 sync per chunk.
// EPI: 0 none, 1 GELU, 2 ReLU, 3 combine, 4 rope-q (scale 1/8), 5 rope-k.
#define SMSH 72
#define HMAT_BYTES (128 * SMSH * 2)
#define HSTAGE_BYTES (2 * HMAT_BYTES)
#define GEMMH_SMEM (2 * HSTAGE_BYTES)
#define RSTR 136      // rope staging stride (halves)

template<int EPI, bool RESID, bool OUTH>
__device__ __forceinline__ void gemmh_body(const __half* __restrict__ A,
                                           const __half* __restrict__ B,
                                           const float* __restrict__ R,
                                           void* __restrict__ Cv,
                                           int N, int K, int bm, int bn,
                                           const __half* __restrict__ R2h = nullptr,
                                           const float* __restrict__ AB = nullptr,
                                           const float2* __restrict__ RT = nullptr) {
    extern __shared__ __half hsmem[];
    const uint32_t sbase = smem_u32(hsmem);

    const int tid = threadIdx.x;
    const int warp = tid >> 5;
    const int lane = tid & 31;
    const int g = lane >> 2;
    const int tg = lane & 3;
    const int sub = lane >> 3;
    const int rin = lane & 7;
    const int wm = (warp & 1) * 64;
    const int wn = (warp >> 1) * 32;

    const int NC = K >> 6;

    auto issue = [&](int kc) {
        const uint32_t ab = sbase + (kc & 1) * HSTAGE_BYTES;
        const uint32_t bb = ab + HMAT_BYTES;
        const int k0 = kc << 6;
#pragma unroll
        for (int i = 0; i < 4; i++) {
            int e = tid + i * 256;
            int r = e >> 3, q8 = e & 7;
            uint32_t soff = (uint32_t)(r * SMSH + q8 * 8) * 2;
            cp16(ab + soff, &A[(size_t)(bm + r) * K + k0 + q8 * 8]);
            cp16(bb + soff, &B[(size_t)(bn + r) * K + k0 + q8 * 8]);
        }
    };

    float acc[4][4][4];
#pragma unroll
    for (int i = 0; i < 4; i++)
#pragma unroll
        for (int j = 0; j < 4; j++)
#pragma unroll
            for (int l = 0; l < 4; l++) acc[i][j][l] = 0.f;

    issue(0); CP_COMMIT();

    for (int kc = 0; kc < NC; kc++) {
        CP_WAIT0();
        __syncthreads();
        if (kc + 1 < NC) {
            issue(kc + 1);
            CP_COMMIT();
        }

        const uint32_t sA = sbase + (kc & 1) * HSTAGE_BYTES;
        const uint32_t sB = sA + HMAT_BYTES;

#pragma unroll
        for (int ks = 0; ks < 4; ks++) {
            uint32_t af[4][4], bf[4][2];
#pragma unroll
            for (int mt = 0; mt < 4; mt++) {
                int row = wm + mt * 16 + rin + (sub & 1) * 8;
                int col = ks * 16 + (sub >> 1) * 8;
                ldsm4(af[mt][0], af[mt][1], af[mt][2], af[mt][3],
                      sA + (uint32_t)(row * SMSH + col) * 2);
            }
#pragma unroll
            for (int p = 0; p < 2; p++) {
                int nrow = wn + (2 * p + (sub >> 1)) * 8 + rin;
                int ncol = ks * 16 + (sub & 1) * 8;
                ldsm4(bf[2 * p][0], bf[2 * p][1], bf[2 * p + 1][0], bf[2 * p + 1][1],
                      sB + (uint32_t)(nrow * SMSH + ncol) * 2);
            }
#pragma unroll
            for (int mt = 0; mt < 4; mt++)
#pragma unroll
                for (int nt = 0; nt < 4; nt++)
                    mma_f16(acc[mt][nt][0], acc[mt][nt][1], acc[mt][nt][2], acc[mt][nt][3],
                            af[mt][0], af[mt][1], af[mt][2], af[mt][3],
                            bf[nt][0], bf[nt][1]);
        }
    }

    if (EPI == 4 || EPI == 5) {
        // ---- fused RoPE epilogue (table-driven): stage tile, rotate pairs, write ----
        __syncthreads();
#pragma unroll
        for (int mt = 0; mt < 4; mt++)
#pragma unroll
            for (int nt = 0; nt < 4; nt++)
#pragma unroll
                for (int half_i = 0; half_i < 2; half_i++) {
                    int rl = wm + mt * 16 + g + half_i * 8;
                    int cl = wn + nt * 8 + tg * 2;
                    *reinterpret_cast<__half2*>(&hsmem[rl * RSTR + cl]) =
                        __floats2half2_rn(acc[mt][nt][half_i * 2 + 0],
                                          acc[mt][nt][half_i * 2 + 1]);
                }
        __syncthreads();
        const float scale = (EPI == 4) ? 0.125f : 1.0f;
        __half* Ch = (__half*)Cv;
#pragma unroll
        for (int j = 0; j < 32; j++) {
            int pidx = tid + j * 256;        // 0..8191
            int r = pidx >> 6;               // 0..127
            int p = pidx & 63;
            int head = p >> 5, i = p & 31;
            int c0 = head * 64 + i, c1 = c0 + 32;
            int m = bm + r;
            int t = m & (TSEQ - 1);
            float2 cs = RT[t * 32 + i];
            float h0 = __half2float(hsmem[r * RSTR + c0]);
            float h1 = __half2float(hsmem[r * RSTR + c1]);
            Ch[(size_t)m * DMODEL + bn + c0] = __float2half_rn((h0 * cs.x - h1 * cs.y) * scale);
            Ch[(size_t)m * DMODEL + bn + c1] = __float2half_rn((h1 * cs.x + h0 * cs.y) * scale);
        }
        return;
    }

#pragma unroll
    for (int mt = 0; mt < 4; mt++) {
#pragma unroll
        for (int nt = 0; nt < 4; nt++) {
            int row = bm + wm + mt * 16 + g;
            int col = bn + wn + nt * 8 + tg * 2;
#pragma unroll
            for (int half_i = 0; half_i < 2; half_i++) {
                int m = row + half_i * 8;
                float v0 = acc[mt][nt][half_i * 2 + 0];
                float v1 = acc[mt][nt][half_i * 2 + 1];
                if (EPI == 1) {
                    v0 = 0.5f * v0 * (1.f + erff(v0 * 0.70710678118f));
                    v1 = 0.5f * v1 * (1.f + erff(v1 * 0.70710678118f));
                }
                if (EPI == 2) { v0 = fmaxf(v0, 0.f); v1 = fmaxf(v1, 0.f); }
                if (EPI == 3) {
                    int bidx = m >> 11;
                    float al = AB[bidx * 2], be = AB[bidx * 2 + 1];
                    float2 rx = *reinterpret_cast<const float2*>(&R[(size_t)m * N + col]);
                    __half2 rfh = *reinterpret_cast<const __half2*>(&R2h[(size_t)m * N + col]);
                    float2 rf = __half22float2(rfh);
                    v0 = rx.x + al * rf.x + be * v0;
                    v1 = rx.y + al * rf.y + be * v1;
                }
                if (RESID) {
                    float2 r2 = *reinterpret_cast<const float2*>(&R[(size_t)m * N + col]);
                    v0 += r2.x; v1 += r2.y;
                }
                if (OUTH) {
                    __half2 hv = __floats2half2_rn(v0, v1);
                    *reinterpret_cast<__half2*>(&((__half*)Cv)[(size_t)m * N + col]) = hv;
                } else {
                    *reinterpret_cast<float2*>(&((float*)Cv)[(size_t)m * N + col]) =
                        make_float2(v0, v1);
                }
            }
        }
    }
}

template<int EPI, bool RESID, bool OUTH>
__global__ void __launch_bounds__(256, 2) gemmh(const __half* __restrict__ A,
                                                const __half* __restrict__ B,
                                                const float* __restrict__ R,
                                                void* __restrict__ C,
                                                int N, int K) {
    gemmh_body<EPI, RESID, OUTH>(A, B, R, C, N, K, blockIdx.y * 128, blockIdx.x * 128);
}

__global__ void __launch_bounds__(256, 2) gemmh_up_combine(const __half* __restrict__ A,
                                                           const __half* __restrict__ B,
                                                           const float* __restrict__ x1,
                                                           const __half* __restrict__ ffnh,
                                                           const float* __restrict__ ab,
                                                           float* __restrict__ out) {
    gemmh_body<3, false, false>(A, B, x1, out, DMODEL, BOT,
                                blockIdx.y * 128, blockIdx.x * 128, ffnh, ab);
}

// fused QKV with table-driven epilogue RoPE on q (scaled) and k; v plain fp16
__global__ void __launch_bounds__(256, 2) gemmh_qkv(const __half* __restrict__ A,
                                                    const __half* __restrict__ B0,
                                                    const __half* __restrict__ B1,
                                                    const __half* __restrict__ B2,
                                                    __half* __restrict__ C0,
                                                    __half* __restrict__ C1,
                                                    __half* __restrict__ C2,
                                                    const float2* __restrict__ rtbl) {
    const int sel = blockIdx.x >> 3;
    const int bm = blockIdx.y * 128;
    const int bn = (blockIdx.x & 7) * 128;
    if (sel == 0) {
        gemmh_body<4, false, true>(A, B0, nullptr, C0, DMODEL, DMODEL, bm, bn,
                                   nullptr, nullptr, rtbl);
    } else if (sel == 1) {
        gemmh_body<5, false, true>(A, B1, nullptr, C1, DMODEL, DMODEL, bm, bn,
                                   nullptr, nullptr, rtbl);
    } else {
        gemmh_body<0, false, true>(A, B2, nullptr, C2, DMODEL, DMODEL, bm, bn);
    }
}

__global__ void __launch_bounds__(256, 2) gemmh_w1_down(const __half* __restrict__ A,
                                                        const __half* __restrict__ w1,
                                                        const __half* __restrict__ down,
                                                        __half* __restrict__ hid,
                                                        __half* __restrict__ ph) {
    if (blockIdx.x < 32) {
        gemmh_body<1, false, true>(A, w1, nullptr, hid, DFF, DMODEL,
                                   blockIdx.y * 128, blockIdx.x * 128);
    } else {
        gemmh_body<2, false, true>(A, down, nullptr, ph, BOT, DMODEL,
                                   blockIdx.y * 128, (blockIdx.x - 32) * 128);
    }
}

// ============ fp16 mma.sync flash attention (causal, K-tile 64, cp.async double-buffered) ============
#define QSTR 72
#define AQ_HALVES (128*QSTR)
#define AT_HALVES (64*QSTR)
#define ATT_SMEM_BYTES ((AQ_HALVES + 4*AT_HALVES) * 2)

__global__ void __launch_bounds__(256, 2) attn_mma_kernel(const __half* __restrict__ Q,
                                                          const __half* __restrict__ K,
                                                          const __half* __restrict__ V,
                                                          __half* __restrict__ O) {
    extern __shared__ __half asmem[];
    const uint32_t sbase = smem_u32(asmem);
    const uint32_t sQ = sbase;

    const int qt = (int)(gridDim.x - 1 - blockIdx.x);
    const int h = blockIdx.y;
    const int b = blockIdx.z;
    const int tid = threadIdx.x;
    const int w = tid >> 5;
    const int lane = tid & 31;
    const int g = lane >> 2;
    const int tg = lane & 3;
    const int sub = lane >> 3;
    const int rin = lane & 7;
    const size_t headoff = (size_t)h * DHEAD;

    auto issue = [&](int kb, int buf) {
        const uint32_t kb_base = sbase + (AQ_HALVES + buf * AT_HALVES) * 2;
        const uint32_t vb_base = sbase + (AQ_HALVES + (2 + buf) * AT_HALVES) * 2;
#pragma unroll
        for (int i = 0; i < 2; i++) {
            int e = tid + i * 256;
            int r = e >> 3, c8 = e & 7;
            size_t gb = ((size_t)(b * TSEQ + kb * 64 + r)) * DMODEL + headoff + c8 * 8;
            uint32_t soff = (uint32_t)(r * QSTR + c8 * 8) * 2;
            cp16(kb_base + soff, &K[gb]);
            cp16(vb_base + soff, &V[gb]);
        }
    };

    issue(0, 0);
#pragma unroll
    for (int i = 0; i < 4; i++) {
        int e = tid + i * 256;
        int r = e >> 3, c8 = e & 7;
        size_t gb = ((size_t)(b * TSEQ + qt * 128 + r)) * DMODEL + headoff + c8 * 8;
        cp16(sQ + (uint32_t)(r * QSTR + c8 * 8) * 2, &Q[gb]);
    }
    CP_COMMIT();
    CP_WAIT0();
    __syncthreads();

    uint32_t qf[4][4];
#pragma unroll
    for (int ks = 0; ks < 4; ks++) {
        int row = w * 16 + rin + (sub & 1) * 8;
        int col = ks * 16 + (sub >> 1) * 8;
        ldsm4(qf[ks][0], qf[ks][1], qf[ks][2], qf[ks][3],
              sQ + (uint32_t)(row * QSTR + col) * 2);
    }

    float o[8][4];
#pragma unroll
    for (int nt = 0; nt < 8; nt++)
#pragma unroll
        for (int l = 0; l < 4; l++) o[nt][l] = 0.f;
    float m0 = -1e30f, m1 = -1e30f, l0 = 0.f, l1 = 0.f;

    const int rowg = qt * 128 + w * 16 + g;
    const int kbmax = 2 * qt + 1;

    for (int kb = 0; kb <= kbmax; kb++) {
        CP_WAIT0();
        __syncthreads();
        if (kb < kbmax) {
            issue(kb + 1, (kb + 1) & 1);
            CP_COMMIT();
        }
        if (kb * 64 > qt * 128 + w * 16 + 15) continue;

        const uint32_t sK = sbase + (AQ_HALVES + (kb & 1) * AT_HALVES) * 2;
        const uint32_t sV = sbase + (AQ_HALVES + (2 + (kb & 1)) * AT_HALVES) * 2;

        float s[8][4];
#pragma unroll
        for (int nt = 0; nt < 8; nt++)
#pragma unroll
            for (int l = 0; l < 4; l++) s[nt][l] = 0.f;
#pragma unroll
        for (int ks = 0; ks < 4; ks++) {
            uint32_t bf[8][2];
#pragma unroll
            for (int p = 0; p < 4; p++) {
                int nrow = (2 * p + (sub >> 1)) * 8 + rin;
                int ncol = ks * 16 + (sub & 1) * 8;
                ldsm4(bf[2 * p][0], bf[2 * p][1], bf[2 * p + 1][0], bf[2 * p + 1][1],
                      sK + (uint32_t)(nrow * QSTR + ncol) * 2);
            }
#pragma unroll
            for (int nt = 0; nt < 8; nt++)
                mma_f16(s[nt][0], s[nt][1], s[nt][2], s[nt][3],
                        qf[ks][0], qf[ks][1], qf[ks][2], qf[ks][3],
                        bf[nt][0], bf[nt][1]);
        }

        if (kb * 64 + 63 > rowg) {
#pragma unroll
            for (int nt = 0; nt < 8; nt++) {
                int c = kb * 64 + nt * 8 + 2 * tg;
                if (c > rowg) s[nt][0] = -1e30f;
                if (c + 1 > rowg) s[nt][1] = -1e30f;
                if (c > rowg + 8) s[nt][2] = -1e30f;
                if (c + 1 > rowg + 8) s[nt][3] = -1e30f;
            }
        }

        float mx0 = -1e30f, mx1 = -1e30f;
#pragma unroll
        for (int nt = 0; nt < 8; nt++) {
            mx0 = fmaxf(mx0, fmaxf(s[nt][0], s[nt][1]));
            mx1 = fmaxf(mx1, fmaxf(s[nt][2], s[nt][3]));
        }
        mx0 = fmaxf(mx0, __shfl_xor_sync(0xffffffffu, mx0, 1));
        mx0 = fmaxf(mx0, __shfl_xor_sync(0xffffffffu, mx0, 2));
        mx1 = fmaxf(mx1, __shfl_xor_sync(0xffffffffu, mx1, 1));
        mx1 = fmaxf(mx1, __shfl_xor_sync(0xffffffffu, mx1, 2));
        float nm0 = fmaxf(m0, mx0), nm1 = fmaxf(m1, mx1);
        float sc0 = __expf(m0 - nm0), sc1 = __expf(m1 - nm1);
        m0 = nm0; m1 = nm1;
        float sum0 = 0.f, sum1 = 0.f;
        uint32_t pf[4][4];
#pragma unroll
        for (int nt = 0; nt < 8; nt++) {
            float p0 = __expf(s[nt][0] - nm0);
            float p1 = __expf(s[nt][1] - nm0);
            float p2 = __expf(s[nt][2] - nm1);
            float p3 = __expf(s[nt][3] - nm1);
            sum0 += p0 + p1; sum1 += p2 + p3;
            int ks = nt >> 1;
            if ((nt & 1) == 0) {
                pf[ks][0] = packh2(p0, p1);
                pf[ks][1] = packh2(p2, p3);
            } else {
                pf[ks][2] = packh2(p0, p1);
                pf[ks][3] = packh2(p2, p3);
            }
        }
        sum0 += __shfl_xor_sync(0xffffffffu, sum0, 1);
        sum0 += __shfl_xor_sync(0xffffffffu, sum0, 2);
        sum1 += __shfl_xor_sync(0xffffffffu, sum1, 1);
        sum1 += __shfl_xor_sync(0xffffffffu, sum1, 2);
        l0 = l0 * sc0 + sum0;
        l1 = l1 * sc1 + sum1;
#pragma unroll
        for (int nt = 0; nt < 8; nt++) {
            o[nt][0] *= sc0; o[nt][1] *= sc0;
            o[nt][2] *= sc1; o[nt][3] *= sc1;
        }

#pragma unroll
        for (int ks = 0; ks < 4; ks++) {
            uint32_t vf[8][2];
#pragma unroll
            for (int np = 0; np < 4; np++) {
                int krow = ks * 16 + ((sub & 1) * 8) + rin;
                int ncol = np * 16 + (sub >> 1) * 8;
                ldsm4t(vf[2 * np][0], vf[2 * np][1], vf[2 * np + 1][0], vf[2 * np + 1][1],
                       sV + (uint32_t)(krow * QSTR + ncol) * 2);
            }
#pragma unroll
            for (int nt = 0; nt < 8; nt++)
                mma_f16(o[nt][0], o[nt][1], o[nt][2], o[nt][3],
                        pf[ks][0], pf[ks][1], pf[ks][2], pf[ks][3],
                        vf[nt][0], vf[nt][1]);
        }
    }

    float il0 = 1.f / l0, il1 = 1.f / l1;
    const size_t rg = (size_t)(b * TSEQ + qt * 128 + w * 16 + g);
#pragma unroll
    for (int nt = 0; nt < 8; nt++) {
        size_t col = headoff + nt * 8 + 2 * tg;
        *reinterpret_cast<__half2*>(&O[rg * DMODEL + col]) =
            __floats2half2_rn(o[nt][0] * il0, o[nt][1] * il0);
        *reinterpret_cast<__half2*>(&O[(rg + 8) * DMODEL + col]) =
            __floats2half2_rn(o[nt][2] * il1, o[nt][3] * il1);
    }
}

// ---------------- RMSNorm (fp32 in, fp16 out) ----------------
__global__ void __launch_bounds__(256) rmsnorm_kernel(const float* __restrict__ x,
                                                      const float* __restrict__ w,
                                                      __half* __restrict__ out) {
    const int row = blockIdx.x;
    const float* xr = x + (size_t)row * DMODEL;
    __half* orow = out + (size_t)row * DMODEL;
    const int tid = threadIdx.x;

    float vals[4];
    float local = 0.f;
#pragma unroll
    for (int i = 0; i < 4; i++) {
        float v = xr[tid + i * 256];
        vals[i] = v;
        local += v * v;
    }
    for (int off = 16; off; off >>= 1) local += __shfl_xor_sync(0xffffffffu, local, off);
    __shared__ float red[8];
    __shared__ float rinv_s;
    int warp = tid >> 5, lane = tid & 31;
    if (lane == 0) red[warp] = local;
    __syncthreads();
    if (tid == 0) {
        float tot = 0.f;
#pragma unroll
        for (int i = 0; i < 8; i++) tot += red[i];
        rinv_s = rsqrtf(tot * (1.0f / DMODEL) + EPS);
    }
    __syncthreads();
    float rinv = rinv_s;
#pragma unroll
    for (int i = 0; i < 4; i++) {
        int c = tid + i * 256;
        orow[c] = __float2half_rn(vals[i] * rinv * w[c]);
    }
}

// ---------------- mean over tokens pass 1 (fp16 input, half2-vectorized) ----------------
__global__ void mean_pass1(const __half* __restrict__ n2, float* __restrict__ gpart) {
    int b = blockIdx.y;
    int tc = blockIdx.z;
    int d2 = blockIdx.x * 256 + threadIdx.x;
    const __half2* p = reinterpret_cast<const __half2*>(
        n2 + (size_t)b * TSEQ * DMODEL + (size_t)tc * 256 * DMODEL) + d2;
    float sx = 0.f, sy = 0.f;
    for (int t = 0; t < 256; t++) {
        float2 v = __half22float2(p[(size_t)t * (DMODEL / 2)]);
        sx += v.x; sy += v.y;
    }
    float2* gp = reinterpret_cast<float2*>(gpart + ((size_t)tc * BATCH + b) * DMODEL);
    gp[d2] = make_float2(sx, sy);
}

// ---------------- fused mean pass 2 + alpha/beta MLP (single block) ----------------
__global__ void __launch_bounds__(256) mean2_ab_kernel(const float* __restrict__ gpart,
                                                       const float* __restrict__ fc1,
                                                       const float* __restrict__ fc2,
                                                       float* __restrict__ ab) {
    __shared__ float gv[BATCH * DMODEL];
    __shared__ float hs[BATCH][ABH];
    const int tid = threadIdx.x;
    for (int i = tid; i < BATCH * DMODEL; i += 256) {
        float s = 0.f;
#pragma unroll
        for (int tc = 0; tc < 8; tc++) s += gpart[(size_t)tc * BATCH * DMODEL + i];
        gv[i] = s * (1.f / TSEQ);
    }
    __syncthreads();
    if (tid < 128) {
        int b = tid >> 5, hh = tid & 31;
        float s = 0.f;
        for (int d = 0; d < DMODEL; d++) s += gv[b * DMODEL + d] * fc1[hh * DMODEL + d];
        hs[b][hh] = fmaxf(s, 0.f);
    }
    __syncthreads();
    if (tid < 2 * BATCH) {
        int bb = tid >> 1, o = tid & 1;
        float s2 = 0.f;
#pragma unroll
        for (int j = 0; j < ABH; j++) s2 += hs[bb][j] * fc2[o * ABH + j];
        ab[bb * 2 + o] = 1.f / (1.f + expf(-s2));
    }
}

// ---------------- launch ----------------
extern "C" void kernel_launch(void* const* d_in, const int* in_sizes, int n_in,
                              void* d_out, int out_size) {
    const float* x       = (const float*)d_in[0];
    const float* norm1_w = (const float*)d_in[2];
    const float* Wq      = (const float*)d_in[3];
    const float* Wk      = (const float*)d_in[4];
    const float* Wv      = (const float*)d_in[5];
    const float* Wo      = (const float*)d_in[6];
    const float* norm2_w = (const float*)d_in[7];
    const float* w1      = (const float*)d_in[8];
    const float* w2      = (const float*)d_in[9];
    const float* fc1     = (const float*)d_in[10];
    const float* fc2     = (const float*)d_in[11];
    const float* down    = (const float*)d_in[12];
    const float* up      = (const float*)d_in[13];
    float* out = (float*)d_out;

    __half *xn1h, *qh, *kh, *vh, *atth, *n2h, *hidh, *ffnh, *phh, *hWall;
    float *x1, *gpart, *ab;
    float2* rtbl;
    cudaGetSymbolAddress((void**)&xn1h,  g_xn1h);
    cudaGetSymbolAddress((void**)&qh,    g_qh);
    cudaGetSymbolAddress((void**)&kh,    g_kh);
    cudaGetSymbolAddress((void**)&vh,    g_vh);
    cudaGetSymbolAddress((void**)&atth,  g_atth);
    cudaGetSymbolAddress((void**)&x1,    g_x1);
    cudaGetSymbolAddress((void**)&n2h,   g_n2h);
    cudaGetSymbolAddress((void**)&hidh,  g_hidh);
    cudaGetSymbolAddress((void**)&ffnh,  g_ffnh);
    cudaGetSymbolAddress((void**)&phh,   g_phh);
    cudaGetSymbolAddress((void**)&gpart, g_gpart);
    cudaGetSymbolAddress((void**)&ab,    g_ab);
    cudaGetSymbolAddress((void**)&rtbl,  g_rtbl);
    cudaGetSymbolAddress((void**)&hWall, g_hWall);

    const __half* hWq   = hWall;
    const __half* hWk   = hWall + 1048576;
    const __half* hWv   = hWall + 2097152;
    const __half* hWo   = hWall + 3145728;
    const __half* hw1   = hWall + 4194304;
    const __half* hw2   = hWall + 8388608;
    const __half* hdown = hWall + 12582912;
    const __half* hup   = hWall + 12845056;

    static bool attr_set = false;
    if (!attr_set) {
        cudaFuncSetAttribute((const void*)attn_mma_kernel,
                             cudaFuncAttributeMaxDynamicSharedMemorySize, ATT_SMEM_BYTES);
        cudaFuncSetAttribute((const void*)gemmh<0, true, false>,
                             cudaFuncAttributeMaxDynamicSharedMemorySize, GEMMH_SMEM);
        cudaFuncSetAttribute((const void*)gemmh<0, false, true>,
                             cudaFuncAttributeMaxDynamicSharedMemorySize, GEMMH_SMEM);
        cudaFuncSetAttribute((const void*)gemmh_qkv,
                             cudaFuncAttributeMaxDynamicSharedMemorySize, GEMMH_SMEM);
        cudaFuncSetAttribute((const void*)gemmh_up_combine,
                             cudaFuncAttributeMaxDynamicSharedMemorySize, GEMMH_SMEM);
        cudaFuncSetAttribute((const void*)gemmh_w1_down,
                             cudaFuncAttributeMaxDynamicSharedMemorySize, GEMMH_SMEM);
        attr_set = true;
    }

    // 0. rope table + convert all weights to fp16
    rope_tbl_kernel<<<TSEQ * 32 / 256, 256>>>(rtbl);
    SrcPtrs sp;
    sp.p[0] = (const float4*)Wq;  sp.p[1] = (const float4*)Wk;
    sp.p[2] = (const float4*)Wv;  sp.p[3] = (const float4*)Wo;
    sp.p[4] = (const float4*)w1;  sp.p[5] = (const float4*)w2;
    sp.p[6] = (const float4*)down; sp.p[7] = (const float4*)up;
    f2h_all_kernel<<<3200, 256>>>(sp, (uint2*)hWall);

    // 1. norm1 (fp16 out)
    rmsnorm_kernel<<<BT, 256>>>(x, norm1_w, xn1h);
    // 2. fused QKV + table-driven epilogue RoPE
    gemmh_qkv<<<dim3(24, BT / 128), 256, GEMMH_SMEM>>>(xn1h, hWq, hWk, hWv, qh, kh, vh, rtbl);
    // 3. attention (fp16 mma flash, K-tile 64)
    attn_mma_kernel<<<dim3(TSEQ / 128, NHEADS, BATCH), 256, ATT_SMEM_BYTES>>>(qh, kh, vh, atth);
    // 4. output proj + residual (fp32 out)
    gemmh<0, true, false><<<dim3(DMODEL / 128, BT / 128), 256, GEMMH_SMEM>>>(atth, hWo, x, x1, DMODEL, DMODEL);
    // 5. norm2 (fp16 out)
    rmsnorm_kernel<<<BT, 256>>>(x1, norm2_w, n2h);
    // 6. alpha/beta gate
    mean_pass1<<<dim3(DMODEL / 512, BATCH, 8), 256>>>(n2h, gpart);
    mean2_ab_kernel<<<1, 256>>>(gpart, fc1, fc2, ab);
    // 7. merged w1(+GELU) and down(+ReLU)
    gemmh_w1_down<<<dim3(34, BT / 128), 256, GEMMH_SMEM>>>(n2h, hw1, hdown, hidh, phh);
    // 8. w2 (fp16 ffn out)
    gemmh<0, false, true><<<dim3(DMODEL / 128, BT / 128), 256, GEMMH_SMEM>>>(hidh, hw2, nullptr, ffnh, DMODEL, DFF);
    // 9. up-proj + fused combine -> out
    gemmh_up_combine<<<dim3(DMODEL / 128, BT / 128), 256, GEMMH_SMEM>>>(phh, hup, x1, ffnh, ab, out);
}